// round 9
// baseline (speedup 1.0000x reference)
#include <cuda_runtime.h>
#include <cstdint>
#include <cstddef>

// ---------------------------------------------------------------------------
// LSTM_FEAT_3: 2-layer LSTM (H=1536), T=2048 sequential steps with softmax->
// embedding feedback. Persistent kernel, 128 CTAs (1/SM), custom grid barrier.
//
// Phases per step (3 grid barriers):
//   A: gates0 = Wih0@xt + Whh0@h0 + b     and   part1 = Whh1@h1 + b
//      -> elementwise cell update (local, CTA owns 12 cells) -> h0n to gmem
//   B: gates1 = part1 + Wih1@h0n -> cell update -> h1n to gmem
//   U: u[c] = Wcomb_row(c) @ h1n + bcomb[c]      (Wcomb = Wout@Whl, precomputed)
//   E: softmax(u) -> y (CTA0 writes output row), emb = Wmap@y  (redundant/CTA,
//      Wmap^T resident in SMEM)  -> feeds next step's xt. No barrier needed.
// ---------------------------------------------------------------------------

#define T_STEPS 2048
#define IN_DIM  118
#define EMBED   128
#define XT_DIM  246     // IN_DIM + EMBED
#define HID     1536
#define HID2    1024
#define OUTD    128
#define NCTA    128
#define NTH     512
#define NWARP   16
#define CELLS   12      // cells per CTA (128*12 = 1536)
#define ROWS0   48      // gate rows per CTA (4 gates * 12 cells)

// ------------------------- device scratch (static, no allocs) ---------------
__device__ float g_Wcomb[OUTD * HID];   // 768 KB
__device__ float g_bcomb[OUTD];
__device__ float g_h0buf[HID];
__device__ float g_h1buf[HID];
__device__ float g_u[OUTD];
__device__ int   g_arrive[NCTA];
__device__ int   g_release;

// ------------------------- SMEM layout (floats) -----------------------------
constexpr int OFF_WMAPT = 0;                         // 128*128 Wmap transposed
constexpr int OFF_WIH0  = OFF_WMAPT + 128 * 128;     // 48*246  Wih0 rows cache
constexpr int OFF_WCOMB = OFF_WIH0 + ROWS0 * XT_DIM; // 1536    Wcomb row
constexpr int OFF_H0    = OFF_WCOMB + HID;           // 1536
constexpr int OFF_H1    = OFF_H0 + HID;              // 1536
constexpr int OFF_XT    = OFF_H1 + HID;              // 256 (118 x | 128 emb)
constexpr int OFF_B0    = OFF_XT + 256;              // 48
constexpr int OFF_B1    = OFF_B0 + ROWS0;            // 48
constexpr int OFF_G0    = OFF_B1 + ROWS0;            // 48
constexpr int OFF_P1    = OFF_G0 + ROWS0;            // 48
constexpr int OFF_C0    = OFF_P1 + ROWS0;            // 12
constexpr int OFF_C1    = OFF_C0 + CELLS;            // 12
constexpr int OFF_BMAP  = OFF_C1 + CELLS;            // 128
constexpr int OFF_Y     = OFF_BMAP + 128;            // 128
constexpr int OFF_U     = OFF_Y + 128;               // 128
constexpr int OFF_RED   = OFF_U + 128;               // 32
constexpr int SMEM_FLOATS = OFF_RED + 32;            // 33688 floats
constexpr int SMEM_BYTES  = SMEM_FLOATS * 4;         // 134752 B

// ------------------------- helpers ------------------------------------------
__device__ __forceinline__ void st_release_gpu(int* p, int v) {
    asm volatile("st.release.gpu.b32 [%0], %1;" :: "l"(p), "r"(v) : "memory");
}
__device__ __forceinline__ int ld_acquire_gpu(int* p) {
    int v;
    asm volatile("ld.acquire.gpu.b32 %0, [%1];" : "=r"(v) : "l"(p) : "memory");
    return v;
}
__device__ __forceinline__ float warp_sum(float v) {
    #pragma unroll
    for (int o = 16; o > 0; o >>= 1) v += __shfl_xor_sync(0xFFFFFFFFu, v, o);
    return v;
}
__device__ __forceinline__ float warp_max(float v) {
    #pragma unroll
    for (int o = 16; o > 0; o >>= 1) v = fmaxf(v, __shfl_xor_sync(0xFFFFFFFFu, v, o));
    return v;
}
__device__ __forceinline__ float sigmoidf_(float x) {
    return 1.0f / (1.0f + expf(-x));
}

// grid-wide barrier: distributed arrive slots + CTA0 gather + release flag
__device__ __forceinline__ void grid_barrier(int epoch) {
    int tid = threadIdx.x;
    int cta = blockIdx.x;
    __syncthreads();                       // all local work done
    if (tid == 0) st_release_gpu(&g_arrive[cta], epoch);
    if (cta == 0) {
        bool ok;
        do {
            ok = true;
            if (tid < NCTA) ok = (ld_acquire_gpu(&g_arrive[tid]) >= epoch);
        } while (!__syncthreads_and(ok));
        if (tid == 0) st_release_gpu(&g_release, epoch);
        // CTA0 threads already synchronized by the loop's __syncthreads_and;
        // tid<128 performed acquires covering all producers.
    } else {
        if (tid == 0) {
            while (ld_acquire_gpu(&g_release) < epoch) { }
        }
        __syncthreads();
    }
}

// warp-cooperative dot over a 1536-vector: gmem row (float4) x smem vector
__device__ __forceinline__ float dot1536(const float* __restrict__ gW,
                                         const float* __restrict__ sv,
                                         int lane) {
    const float4* w4 = reinterpret_cast<const float4*>(gW);
    const float4* v4 = reinterpret_cast<const float4*>(sv);
    float s = 0.f;
    #pragma unroll
    for (int i = 0; i < 12; i++) {
        float4 w = __ldg(w4 + lane + 32 * i);
        float4 v = v4[lane + 32 * i];
        s += w.x * v.x + w.y * v.y + w.z * v.z + w.w * v.w;
    }
    return s;
}

// ------------------------- prep kernels -------------------------------------
__global__ void init_barrier_kernel() {
    int i = threadIdx.x;
    if (i < NCTA) g_arrive[i] = 0;
    if (i == 0) g_release = 0;
}

// Wcomb[c][k] = sum_m Wout[c][m] * Whl[m][k]   (128 x 1536, m over 1024)
__global__ void wcomb_kernel(const float* __restrict__ Wout,
                             const float* __restrict__ Whl) {
    __shared__ float s_wout[HID2];
    int c = blockIdx.y;
    int k = blockIdx.x * 256 + threadIdx.x;
    for (int i = threadIdx.x; i < HID2; i += 256)
        s_wout[i] = __ldg(&Wout[c * HID2 + i]);
    __syncthreads();
    float acc = 0.f;
    #pragma unroll 8
    for (int m = 0; m < HID2; m++)
        acc += s_wout[m] * __ldg(&Whl[(size_t)m * HID + k]);
    g_Wcomb[c * HID + k] = acc;
}

// bcomb[c] = bout[c] + sum_m Wout[c][m] * bhl[m]
__global__ void bcomb_kernel(const float* __restrict__ Wout,
                             const float* __restrict__ bhl,
                             const float* __restrict__ bout) {
    __shared__ float s_bhl[HID2];
    int c = threadIdx.x;   // 128 threads
    for (int i = c; i < HID2; i += 128) s_bhl[i] = __ldg(&bhl[i]);
    __syncthreads();
    float acc = __ldg(&bout[c]);
    #pragma unroll 8
    for (int m = 0; m < HID2; m++)
        acc += __ldg(&Wout[c * HID2 + m]) * s_bhl[m];
    g_bcomb[c] = acc;
}

// ------------------------- persistent main kernel ---------------------------
__global__ void __launch_bounds__(NTH, 1)
lstm_persistent(const float* __restrict__ x,      // [T,118]
                const float* __restrict__ h0in,   // [2,1536]
                const float* __restrict__ c0in,   // [2,1536]
                const float* __restrict__ Wih0,   // [6144,246]
                const float* __restrict__ Whh0,   // [6144,1536]
                const float* __restrict__ bih0,
                const float* __restrict__ bhh0,
                const float* __restrict__ Wih1,   // [6144,1536]
                const float* __restrict__ Whh1,   // [6144,1536]
                const float* __restrict__ bih1,
                const float* __restrict__ bhh1,
                const float* __restrict__ Wmap,   // [128,128]
                const float* __restrict__ bmap,   // [128]
                float* __restrict__ out)          // [T,128]
{
    extern __shared__ float sm[];
    const int tid   = threadIdx.x;
    const int cta   = blockIdx.x;
    const int warp  = tid >> 5;
    const int lane  = tid & 31;
    const int cell0 = cta * CELLS;

    // ---- one-time per-launch init into SMEM ----
    // Wmap transposed: smT[q*128+e] = Wmap[e*128+q]
    for (int i = tid; i < 128 * 128; i += NTH) {
        int e = i >> 7, q = i & 127;
        sm[OFF_WMAPT + q * 128 + e] = __ldg(&Wmap[i]);
    }
    for (int i = tid; i < 128; i += NTH) sm[OFF_BMAP + i] = __ldg(&bmap[i]);
    // Wih0 rows for this CTA's 48 gate rows
    for (int idx = tid; idx < ROWS0 * XT_DIM; idx += NTH) {
        int tsk = idx / XT_DIM, k = idx - tsk * XT_DIM;
        int l = tsk % CELLS, gq = tsk / CELLS;
        int r = gq * HID + cell0 + l;
        sm[OFF_WIH0 + idx] = __ldg(&Wih0[(size_t)r * XT_DIM + k]);
    }
    // fused biases
    for (int tsk = tid; tsk < ROWS0; tsk += NTH) {
        int l = tsk % CELLS, gq = tsk / CELLS;
        int r = gq * HID + cell0 + l;
        sm[OFF_B0 + tsk] = __ldg(&bih0[r]) + __ldg(&bhh0[r]);
        sm[OFF_B1 + tsk] = __ldg(&bih1[r]) + __ldg(&bhh1[r]);
    }
    // Wcomb row for this CTA (written by prep kernel in this launch)
    for (int i = tid; i < HID; i += NTH)
        sm[OFF_WCOMB + i] = g_Wcomb[cta * HID + i];
    // initial hidden state vectors + cell states
    for (int i = tid; i < HID; i += NTH) {
        sm[OFF_H0 + i] = __ldg(&h0in[i]);
        sm[OFF_H1 + i] = __ldg(&h0in[HID + i]);
    }
    if (tid < CELLS) {
        sm[OFF_C0 + tid] = __ldg(&c0in[cell0 + tid]);
        sm[OFF_C1 + tid] = __ldg(&c0in[HID + cell0 + tid]);
    }
    // emb(0) = 0
    if (tid < EMBED) sm[OFF_XT + IN_DIM + tid] = 0.f;
    __syncthreads();

    int epoch = 0;

    for (int t = 0; t < T_STEPS; t++) {
        // load x_t into xt[0:118]
        if (tid < IN_DIM) sm[OFF_XT + tid] = __ldg(&x[t * IN_DIM + tid]);
        __syncthreads();

        // ---- Phase A: gates0 rows + layer1 partial rows (96 warp-tasks) ----
        for (int i = 0; i < 6; i++) {
            int tsk = i * NWARP + warp;
            if (tsk < ROWS0) {
                int l = tsk % CELLS, gq = tsk / CELLS;
                int r = gq * HID + cell0 + l;
                float s = 0.f;
                const float* wr = &sm[OFF_WIH0 + tsk * XT_DIM];
                #pragma unroll
                for (int k = lane; k < XT_DIM; k += 32)
                    s += wr[k] * sm[OFF_XT + k];
                s += dot1536(Whh0 + (size_t)r * HID, &sm[OFF_H0], lane);
                s = warp_sum(s);
                if (lane == 0) sm[OFF_G0 + tsk] = s + sm[OFF_B0 + tsk];
            } else {
                int tsk2 = tsk - ROWS0;
                int l = tsk2 % CELLS, gq = tsk2 / CELLS;
                int r = gq * HID + cell0 + l;
                float s = dot1536(Whh1 + (size_t)r * HID, &sm[OFF_H1], lane);
                s = warp_sum(s);
                if (lane == 0) sm[OFF_P1 + tsk2] = s + sm[OFF_B1 + tsk2];
            }
        }
        __syncthreads();
        // cell update layer 0 (torch gate order i,f,g,o)
        if (tid < CELLS) {
            int l = tid;
            float ig = sigmoidf_(sm[OFF_G0 + 0 * CELLS + l]);
            float fg = sigmoidf_(sm[OFF_G0 + 1 * CELLS + l]);
            float gg = tanhf    (sm[OFF_G0 + 2 * CELLS + l]);
            float og = sigmoidf_(sm[OFF_G0 + 3 * CELLS + l]);
            float c  = fg * sm[OFF_C0 + l] + ig * gg;
            sm[OFF_C0 + l] = c;
            __stcg(&g_h0buf[cell0 + l], og * tanhf(c));
        }
        epoch++; grid_barrier(epoch);
        // reload full h0n
        for (int i = tid; i < HID; i += NTH)
            sm[OFF_H0 + i] = __ldcg(&g_h0buf[i]);
        __syncthreads();

        // ---- Phase B: gates1 = part1 + Wih1 @ h0n (48 warp-tasks) ----
        for (int i = 0; i < 3; i++) {
            int tsk = i * NWARP + warp;
            int l = tsk % CELLS, gq = tsk / CELLS;
            int r = gq * HID + cell0 + l;
            float s = dot1536(Wih1 + (size_t)r * HID, &sm[OFF_H0], lane);
            s = warp_sum(s);
            if (lane == 0) sm[OFF_G0 + tsk] = sm[OFF_P1 + tsk] + s;
        }
        __syncthreads();
        if (tid < CELLS) {
            int l = tid;
            float ig = sigmoidf_(sm[OFF_G0 + 0 * CELLS + l]);
            float fg = sigmoidf_(sm[OFF_G0 + 1 * CELLS + l]);
            float gg = tanhf    (sm[OFF_G0 + 2 * CELLS + l]);
            float og = sigmoidf_(sm[OFF_G0 + 3 * CELLS + l]);
            float c  = fg * sm[OFF_C1 + l] + ig * gg;
            sm[OFF_C1 + l] = c;
            __stcg(&g_h1buf[cell0 + l], og * tanhf(c));
        }
        epoch++; grid_barrier(epoch);
        for (int i = tid; i < HID; i += NTH)
            sm[OFF_H1 + i] = __ldcg(&g_h1buf[i]);
        __syncthreads();

        // ---- Phase U: u[cta] = Wcomb_row . h1n + bcomb[cta] ----
        {
            float acc = 0.f;
            #pragma unroll
            for (int i = 0; i < 3; i++) {
                int k = tid + i * NTH;
                acc += sm[OFF_WCOMB + k] * sm[OFF_H1 + k];
            }
            acc = warp_sum(acc);
            if (lane == 0) sm[OFF_RED + warp] = acc;
            __syncthreads();
            if (warp == 0) {
                float v = (lane < NWARP) ? sm[OFF_RED + lane] : 0.f;
                v = warp_sum(v);
                if (lane == 0) __stcg(&g_u[cta], v + __ldg(&g_bcomb[cta]));
            }
        }
        epoch++; grid_barrier(epoch);

        // ---- Phase E: softmax + emb (redundant per CTA, no extra barrier) --
        float uval = 0.f;
        if (tid < OUTD) {
            uval = __ldcg(&g_u[tid]);
            sm[OFF_U + tid] = uval;
            float mx = warp_max(uval);
            if (lane == 0) sm[OFF_RED + warp] = mx;   // warps 0..3
        }
        __syncthreads();
        float gmax = fmaxf(fmaxf(sm[OFF_RED + 0], sm[OFF_RED + 1]),
                           fmaxf(sm[OFF_RED + 2], sm[OFF_RED + 3]));
        float ev = 0.f;
        if (tid < OUTD) {
            ev = expf(uval - gmax);
            float ws = warp_sum(ev);
            if (lane == 0) sm[OFF_RED + warp] = ws;
        }
        __syncthreads();
        float gsum = sm[OFF_RED + 0] + sm[OFF_RED + 1] +
                     sm[OFF_RED + 2] + sm[OFF_RED + 3];
        if (tid < OUTD) {
            float y = ev / gsum;
            sm[OFF_Y + tid] = y;
            if (cta == 0) out[(size_t)t * OUTD + tid] = y;
        }
        __syncthreads();
        if (tid < EMBED) {
            float a = sm[OFF_BMAP + tid];
            #pragma unroll 8
            for (int q = 0; q < OUTD; q++)
                a += sm[OFF_WMAPT + q * 128 + tid] * sm[OFF_Y + q];
            sm[OFF_XT + IN_DIM + tid] = a;   // emb feeds next step's xt
        }
        __syncthreads();
    }
}

// ------------------------- launch -------------------------------------------
extern "C" void kernel_launch(void* const* d_in, const int* in_sizes, int n_in,
                              void* d_out, int out_size) {
    (void)in_sizes; (void)n_in; (void)out_size;
    const float* x     = (const float*)d_in[0];
    const float* h0    = (const float*)d_in[1];
    const float* c0    = (const float*)d_in[2];
    const float* Wih0  = (const float*)d_in[3];
    const float* Whh0  = (const float*)d_in[4];
    const float* bih0  = (const float*)d_in[5];
    const float* bhh0  = (const float*)d_in[6];
    const float* Wih1  = (const float*)d_in[7];
    const float* Whh1  = (const float*)d_in[8];
    const float* bih1  = (const float*)d_in[9];
    const float* bhh1  = (const float*)d_in[10];
    const float* Whl   = (const float*)d_in[11];
    const float* bhl   = (const float*)d_in[12];
    const float* Wout  = (const float*)d_in[13];
    const float* bout  = (const float*)d_in[14];
    const float* Wmap  = (const float*)d_in[15];
    const float* bmap  = (const float*)d_in[16];
    float* out = (float*)d_out;

    cudaFuncSetAttribute(lstm_persistent,
                         cudaFuncAttributeMaxDynamicSharedMemorySize,
                         SMEM_BYTES);

    init_barrier_kernel<<<1, 128>>>();
    wcomb_kernel<<<dim3(HID / 256, OUTD), 256>>>(Wout, Whl);
    bcomb_kernel<<<1, 128>>>(Wout, bhl, bout);
    lstm_persistent<<<NCTA, NTH, SMEM_BYTES>>>(
        x, h0, c0, Wih0, Whh0, bih0, bhh0,
        Wih1, Whh1, bih1, bhh1, Wmap, bmap, out);
}

// round 10
// speedup vs baseline: 1.0045x; 1.0045x over previous
#include <cuda_runtime.h>
#include <cstdint>
#include <cstddef>

// ---------------------------------------------------------------------------
// LSTM_FEAT_3: 2-layer LSTM (H=1536), T=2048 sequential steps with softmax->
// embedding feedback. Persistent kernel, 128 CTAs (1/SM), custom grid barrier.
//
// Phases per step (3 grid barriers):
//   A: gates0 = Wih0@xt + Whh0@h0 + b     and   part1 = Whh1@h1 + b
//      -> elementwise cell update (local, CTA owns 12 cells) -> h0n to gmem
//   B: gates1 = part1 + Wih1@h0n -> cell update -> h1n to gmem
//   U: u[c] = Wcomb_row(c) @ h1n + bcomb[c]      (Wcomb = Wout@Whl, precomputed)
//   E: softmax(u) -> y (CTA0 writes output row), emb = Wmap@y  (redundant/CTA,
//      Wmap^T resident in SMEM)  -> feeds next step's xt. No barrier needed.
// ---------------------------------------------------------------------------

#define T_STEPS 2048
#define IN_DIM  118
#define EMBED   128
#define XT_DIM  246     // IN_DIM + EMBED
#define HID     1536
#define HID2    1024
#define OUTD    128
#define NCTA    128
#define NTH     512
#define NWARP   16
#define CELLS   12      // cells per CTA (128*12 = 1536)
#define ROWS0   48      // gate rows per CTA (4 gates * 12 cells)

// ------------------------- device scratch (static, no allocs) ---------------
__device__ float g_Wcomb[OUTD * HID];   // 768 KB
__device__ float g_bcomb[OUTD];
__device__ float g_h0buf[HID];
__device__ float g_h1buf[HID];
__device__ float g_u[OUTD];
__device__ int   g_arrive[NCTA];
__device__ int   g_release;

// ------------------------- SMEM layout (floats) -----------------------------
constexpr int OFF_WMAPT = 0;                         // 128*128 Wmap transposed
constexpr int OFF_WIH0  = OFF_WMAPT + 128 * 128;     // 48*246  Wih0 rows cache
constexpr int OFF_WCOMB = OFF_WIH0 + ROWS0 * XT_DIM; // 1536    Wcomb row
constexpr int OFF_H0    = OFF_WCOMB + HID;           // 1536
constexpr int OFF_H1    = OFF_H0 + HID;              // 1536
constexpr int OFF_XT    = OFF_H1 + HID;              // 256 (118 x | 128 emb)
constexpr int OFF_B0    = OFF_XT + 256;              // 48
constexpr int OFF_B1    = OFF_B0 + ROWS0;            // 48
constexpr int OFF_G0    = OFF_B1 + ROWS0;            // 48
constexpr int OFF_P1    = OFF_G0 + ROWS0;            // 48
constexpr int OFF_C0    = OFF_P1 + ROWS0;            // 12
constexpr int OFF_C1    = OFF_C0 + CELLS;            // 12
constexpr int OFF_BMAP  = OFF_C1 + CELLS;            // 128
constexpr int OFF_Y     = OFF_BMAP + 128;            // 128
constexpr int OFF_U     = OFF_Y + 128;               // 128
constexpr int OFF_RED   = OFF_U + 128;               // 32
constexpr int SMEM_FLOATS = OFF_RED + 32;            // 33688 floats
constexpr int SMEM_BYTES  = SMEM_FLOATS * 4;         // 134752 B

// ------------------------- helpers ------------------------------------------
__device__ __forceinline__ void st_release_gpu(int* p, int v) {
    asm volatile("st.release.gpu.b32 [%0], %1;" :: "l"(p), "r"(v) : "memory");
}
__device__ __forceinline__ int ld_acquire_gpu(int* p) {
    int v;
    asm volatile("ld.acquire.gpu.b32 %0, [%1];" : "=r"(v) : "l"(p) : "memory");
    return v;
}
__device__ __forceinline__ float warp_sum(float v) {
    #pragma unroll
    for (int o = 16; o > 0; o >>= 1) v += __shfl_xor_sync(0xFFFFFFFFu, v, o);
    return v;
}
__device__ __forceinline__ float warp_max(float v) {
    #pragma unroll
    for (int o = 16; o > 0; o >>= 1) v = fmaxf(v, __shfl_xor_sync(0xFFFFFFFFu, v, o));
    return v;
}
__device__ __forceinline__ float sigmoidf_(float x) {
    return 1.0f / (1.0f + expf(-x));
}

// grid-wide barrier: distributed arrive slots + CTA0 gather + release flag
__device__ __forceinline__ void grid_barrier(int epoch) {
    int tid = threadIdx.x;
    int cta = blockIdx.x;
    __syncthreads();                       // all local work done
    if (tid == 0) st_release_gpu(&g_arrive[cta], epoch);
    if (cta == 0) {
        bool ok;
        do {
            ok = true;
            if (tid < NCTA) ok = (ld_acquire_gpu(&g_arrive[tid]) >= epoch);
        } while (!__syncthreads_and(ok));
        if (tid == 0) st_release_gpu(&g_release, epoch);
        // CTA0 threads already synchronized by the loop's __syncthreads_and;
        // tid<128 performed acquires covering all producers.
    } else {
        if (tid == 0) {
            while (ld_acquire_gpu(&g_release) < epoch) { }
        }
        __syncthreads();
    }
}

// warp-cooperative dot over a 1536-vector: gmem row (float4) x smem vector
__device__ __forceinline__ float dot1536(const float* __restrict__ gW,
                                         const float* __restrict__ sv,
                                         int lane) {
    const float4* w4 = reinterpret_cast<const float4*>(gW);
    const float4* v4 = reinterpret_cast<const float4*>(sv);
    float s = 0.f;
    #pragma unroll
    for (int i = 0; i < 12; i++) {
        float4 w = __ldg(w4 + lane + 32 * i);
        float4 v = v4[lane + 32 * i];
        s += w.x * v.x + w.y * v.y + w.z * v.z + w.w * v.w;
    }
    return s;
}

// ------------------------- prep kernels -------------------------------------
__global__ void init_barrier_kernel() {
    int i = threadIdx.x;
    if (i < NCTA) g_arrive[i] = 0;
    if (i == 0) g_release = 0;
}

// Wcomb[c][k] = sum_m Wout[c][m] * Whl[m][k]   (128 x 1536, m over 1024)
__global__ void wcomb_kernel(const float* __restrict__ Wout,
                             const float* __restrict__ Whl) {
    __shared__ float s_wout[HID2];
    int c = blockIdx.y;
    int k = blockIdx.x * 256 + threadIdx.x;
    for (int i = threadIdx.x; i < HID2; i += 256)
        s_wout[i] = __ldg(&Wout[c * HID2 + i]);
    __syncthreads();
    float acc = 0.f;
    #pragma unroll 8
    for (int m = 0; m < HID2; m++)
        acc += s_wout[m] * __ldg(&Whl[(size_t)m * HID + k]);
    g_Wcomb[c * HID + k] = acc;
}

// bcomb[c] = bout[c] + sum_m Wout[c][m] * bhl[m]
__global__ void bcomb_kernel(const float* __restrict__ Wout,
                             const float* __restrict__ bhl,
                             const float* __restrict__ bout) {
    __shared__ float s_bhl[HID2];
    int c = threadIdx.x;   // 128 threads
    for (int i = c; i < HID2; i += 128) s_bhl[i] = __ldg(&bhl[i]);
    __syncthreads();
    float acc = __ldg(&bout[c]);
    #pragma unroll 8
    for (int m = 0; m < HID2; m++)
        acc += __ldg(&Wout[c * HID2 + m]) * s_bhl[m];
    g_bcomb[c] = acc;
}

// ------------------------- persistent main kernel ---------------------------
__global__ void __launch_bounds__(NTH, 1)
lstm_persistent(const float* __restrict__ x,      // [T,118]
                const float* __restrict__ h0in,   // [2,1536]
                const float* __restrict__ c0in,   // [2,1536]
                const float* __restrict__ Wih0,   // [6144,246]
                const float* __restrict__ Whh0,   // [6144,1536]
                const float* __restrict__ bih0,
                const float* __restrict__ bhh0,
                const float* __restrict__ Wih1,   // [6144,1536]
                const float* __restrict__ Whh1,   // [6144,1536]
                const float* __restrict__ bih1,
                const float* __restrict__ bhh1,
                const float* __restrict__ Wmap,   // [128,128]
                const float* __restrict__ bmap,   // [128]
                float* __restrict__ out)          // [T,128]
{
    extern __shared__ float sm[];
    const int tid   = threadIdx.x;
    const int cta   = blockIdx.x;
    const int warp  = tid >> 5;
    const int lane  = tid & 31;
    const int cell0 = cta * CELLS;

    // ---- one-time per-launch init into SMEM ----
    // Wmap transposed: smT[q*128+e] = Wmap[e*128+q]
    for (int i = tid; i < 128 * 128; i += NTH) {
        int e = i >> 7, q = i & 127;
        sm[OFF_WMAPT + q * 128 + e] = __ldg(&Wmap[i]);
    }
    for (int i = tid; i < 128; i += NTH) sm[OFF_BMAP + i] = __ldg(&bmap[i]);
    // Wih0 rows for this CTA's 48 gate rows
    for (int idx = tid; idx < ROWS0 * XT_DIM; idx += NTH) {
        int tsk = idx / XT_DIM, k = idx - tsk * XT_DIM;
        int l = tsk % CELLS, gq = tsk / CELLS;
        int r = gq * HID + cell0 + l;
        sm[OFF_WIH0 + idx] = __ldg(&Wih0[(size_t)r * XT_DIM + k]);
    }
    // fused biases
    for (int tsk = tid; tsk < ROWS0; tsk += NTH) {
        int l = tsk % CELLS, gq = tsk / CELLS;
        int r = gq * HID + cell0 + l;
        sm[OFF_B0 + tsk] = __ldg(&bih0[r]) + __ldg(&bhh0[r]);
        sm[OFF_B1 + tsk] = __ldg(&bih1[r]) + __ldg(&bhh1[r]);
    }
    // Wcomb row for this CTA (written by prep kernel in this launch)
    for (int i = tid; i < HID; i += NTH)
        sm[OFF_WCOMB + i] = g_Wcomb[cta * HID + i];
    // initial hidden state vectors + cell states
    for (int i = tid; i < HID; i += NTH) {
        sm[OFF_H0 + i] = __ldg(&h0in[i]);
        sm[OFF_H1 + i] = __ldg(&h0in[HID + i]);
    }
    if (tid < CELLS) {
        sm[OFF_C0 + tid] = __ldg(&c0in[cell0 + tid]);
        sm[OFF_C1 + tid] = __ldg(&c0in[HID + cell0 + tid]);
    }
    // emb(0) = 0
    if (tid < EMBED) sm[OFF_XT + IN_DIM + tid] = 0.f;
    __syncthreads();

    int epoch = 0;

    for (int t = 0; t < T_STEPS; t++) {
        // load x_t into xt[0:118]
        if (tid < IN_DIM) sm[OFF_XT + tid] = __ldg(&x[t * IN_DIM + tid]);
        __syncthreads();

        // ---- Phase A: gates0 rows + layer1 partial rows (96 warp-tasks) ----
        for (int i = 0; i < 6; i++) {
            int tsk = i * NWARP + warp;
            if (tsk < ROWS0) {
                int l = tsk % CELLS, gq = tsk / CELLS;
                int r = gq * HID + cell0 + l;
                float s = 0.f;
                const float* wr = &sm[OFF_WIH0 + tsk * XT_DIM];
                #pragma unroll
                for (int k = lane; k < XT_DIM; k += 32)
                    s += wr[k] * sm[OFF_XT + k];
                s += dot1536(Whh0 + (size_t)r * HID, &sm[OFF_H0], lane);
                s = warp_sum(s);
                if (lane == 0) sm[OFF_G0 + tsk] = s + sm[OFF_B0 + tsk];
            } else {
                int tsk2 = tsk - ROWS0;
                int l = tsk2 % CELLS, gq = tsk2 / CELLS;
                int r = gq * HID + cell0 + l;
                float s = dot1536(Whh1 + (size_t)r * HID, &sm[OFF_H1], lane);
                s = warp_sum(s);
                if (lane == 0) sm[OFF_P1 + tsk2] = s + sm[OFF_B1 + tsk2];
            }
        }
        __syncthreads();
        // cell update layer 0 (torch gate order i,f,g,o)
        if (tid < CELLS) {
            int l = tid;
            float ig = sigmoidf_(sm[OFF_G0 + 0 * CELLS + l]);
            float fg = sigmoidf_(sm[OFF_G0 + 1 * CELLS + l]);
            float gg = tanhf    (sm[OFF_G0 + 2 * CELLS + l]);
            float og = sigmoidf_(sm[OFF_G0 + 3 * CELLS + l]);
            float c  = fg * sm[OFF_C0 + l] + ig * gg;
            sm[OFF_C0 + l] = c;
            __stcg(&g_h0buf[cell0 + l], og * tanhf(c));
        }
        epoch++; grid_barrier(epoch);
        // reload full h0n
        for (int i = tid; i < HID; i += NTH)
            sm[OFF_H0 + i] = __ldcg(&g_h0buf[i]);
        __syncthreads();

        // ---- Phase B: gates1 = part1 + Wih1 @ h0n (48 warp-tasks) ----
        for (int i = 0; i < 3; i++) {
            int tsk = i * NWARP + warp;
            int l = tsk % CELLS, gq = tsk / CELLS;
            int r = gq * HID + cell0 + l;
            float s = dot1536(Wih1 + (size_t)r * HID, &sm[OFF_H0], lane);
            s = warp_sum(s);
            if (lane == 0) sm[OFF_G0 + tsk] = sm[OFF_P1 + tsk] + s;
        }
        __syncthreads();
        if (tid < CELLS) {
            int l = tid;
            float ig = sigmoidf_(sm[OFF_G0 + 0 * CELLS + l]);
            float fg = sigmoidf_(sm[OFF_G0 + 1 * CELLS + l]);
            float gg = tanhf    (sm[OFF_G0 + 2 * CELLS + l]);
            float og = sigmoidf_(sm[OFF_G0 + 3 * CELLS + l]);
            float c  = fg * sm[OFF_C1 + l] + ig * gg;
            sm[OFF_C1 + l] = c;
            __stcg(&g_h1buf[cell0 + l], og * tanhf(c));
        }
        epoch++; grid_barrier(epoch);
        for (int i = tid; i < HID; i += NTH)
            sm[OFF_H1 + i] = __ldcg(&g_h1buf[i]);
        __syncthreads();

        // ---- Phase U: u[cta] = Wcomb_row . h1n + bcomb[cta] ----
        {
            float acc = 0.f;
            #pragma unroll
            for (int i = 0; i < 3; i++) {
                int k = tid + i * NTH;
                acc += sm[OFF_WCOMB + k] * sm[OFF_H1 + k];
            }
            acc = warp_sum(acc);
            if (lane == 0) sm[OFF_RED + warp] = acc;
            __syncthreads();
            if (warp == 0) {
                float v = (lane < NWARP) ? sm[OFF_RED + lane] : 0.f;
                v = warp_sum(v);
                if (lane == 0) __stcg(&g_u[cta], v + __ldg(&g_bcomb[cta]));
            }
        }
        epoch++; grid_barrier(epoch);

        // ---- Phase E: softmax + emb (redundant per CTA, no extra barrier) --
        float uval = 0.f;
        if (tid < OUTD) {
            uval = __ldcg(&g_u[tid]);
            sm[OFF_U + tid] = uval;
            float mx = warp_max(uval);
            if (lane == 0) sm[OFF_RED + warp] = mx;   // warps 0..3
        }
        __syncthreads();
        float gmax = fmaxf(fmaxf(sm[OFF_RED + 0], sm[OFF_RED + 1]),
                           fmaxf(sm[OFF_RED + 2], sm[OFF_RED + 3]));
        float ev = 0.f;
        if (tid < OUTD) {
            ev = expf(uval - gmax);
            float ws = warp_sum(ev);
            if (lane == 0) sm[OFF_RED + warp] = ws;
        }
        __syncthreads();
        float gsum = sm[OFF_RED + 0] + sm[OFF_RED + 1] +
                     sm[OFF_RED + 2] + sm[OFF_RED + 3];
        if (tid < OUTD) {
            float y = ev / gsum;
            sm[OFF_Y + tid] = y;
            if (cta == 0) out[(size_t)t * OUTD + tid] = y;
        }
        __syncthreads();
        if (tid < EMBED) {
            float a = sm[OFF_BMAP + tid];
            #pragma unroll 8
            for (int q = 0; q < OUTD; q++)
                a += sm[OFF_WMAPT + q * 128 + tid] * sm[OFF_Y + q];
            sm[OFF_XT + IN_DIM + tid] = a;   // emb feeds next step's xt
        }
        __syncthreads();
    }
}

// ------------------------- launch -------------------------------------------
extern "C" void kernel_launch(void* const* d_in, const int* in_sizes, int n_in,
                              void* d_out, int out_size) {
    (void)in_sizes; (void)n_in; (void)out_size;
    const float* x     = (const float*)d_in[0];
    const float* h0    = (const float*)d_in[1];
    const float* c0    = (const float*)d_in[2];
    const float* Wih0  = (const float*)d_in[3];
    const float* Whh0  = (const float*)d_in[4];
    const float* bih0  = (const float*)d_in[5];
    const float* bhh0  = (const float*)d_in[6];
    const float* Wih1  = (const float*)d_in[7];
    const float* Whh1  = (const float*)d_in[8];
    const float* bih1  = (const float*)d_in[9];
    const float* bhh1  = (const float*)d_in[10];
    const float* Whl   = (const float*)d_in[11];
    const float* bhl   = (const float*)d_in[12];
    const float* Wout  = (const float*)d_in[13];
    const float* bout  = (const float*)d_in[14];
    const float* Wmap  = (const float*)d_in[15];
    const float* bmap  = (const float*)d_in[16];
    float* out = (float*)d_out;

    cudaFuncSetAttribute(lstm_persistent,
                         cudaFuncAttributeMaxDynamicSharedMemorySize,
                         SMEM_BYTES);

    init_barrier_kernel<<<1, 128>>>();
    wcomb_kernel<<<dim3(HID / 256, OUTD), 256>>>(Wout, Whl);
    bcomb_kernel<<<1, 128>>>(Wout, bhl, bout);
    lstm_persistent<<<NCTA, NTH, SMEM_BYTES>>>(
        x, h0, c0, Wih0, Whh0, bih0, bhh0,
        Wih1, Whh1, bih1, bhh1, Wmap, bmap, out);
}